// round 9
// baseline (speedup 1.0000x reference)
#include <cuda_runtime.h>
#include <cuda_bf16.h>
#include <cstdint>

typedef unsigned int u32;

// ============================================================================
// CustomLinear fused q/k/v — mma.sync bf16 hi/lo split, global-direct fragments
//   Warp tile = 32 feats x 64 tokens (2 m16 row-tiles, 8 n8 col-tiles).
//   CTA = 128 feats x 128 tokens; grid (tokens/128, 8 GEMMs). No smem, no syncs.
//   k-interleave within 16-k chunk: [0,1,8,9, 2,3,10,11, 4,5,12,13, 6,7,14,15]
// ============================================================================

#define REGION 34078720L           // 8*4096*1040 floats per q/k/v region
#define NTOK   32768

__device__ __align__(16) __nv_bfloat16 g_Wh[8 * 8192];
__device__ __align__(16) __nv_bfloat16 g_Wl[8 * 8192];
__device__ __align__(16) __nv_bfloat16 g_X[4][NTOK * 64];   // 0 x1h 1 x1l 2 x2h 3 x2l
__device__ __align__(16) float2 g_S[NTOK];                  // {s_mid, s_last}

__device__ __forceinline__ int kpos(int kk) {               // kk in 0..15
    return (((kk & 7) >> 1) << 2) + ((kk >> 3) << 1) + (kk & 1);
}

__device__ __forceinline__ void mma_bf16(float* c,
                                         u32 a0, u32 a1, u32 a2, u32 a3,
                                         u32 b0, u32 b1) {
    asm volatile(
        "mma.sync.aligned.m16n8k16.row.col.f32.bf16.bf16.f32 "
        "{%0,%1,%2,%3}, {%4,%5,%6,%7}, {%8,%9}, {%0,%1,%2,%3};"
        : "+f"(c[0]), "+f"(c[1]), "+f"(c[2]), "+f"(c[3])
        : "r"(a0), "r"(a1), "r"(a2), "r"(a3), "r"(b0), "r"(b1));
}

// ---- prep W: 32 blocks, each does a quarter of one packed GEMM ----
__global__ void prep_w(const float* __restrict__ Mq, const float* __restrict__ Mk,
                       const float* __restrict__ Mv) {
    int g = blockIdx.x >> 2, quarter = blockIdx.x & 3;
    int r = (g < 2) ? 0 : (g < 4) ? 1 : 2;
    int p = (g < 2) ? g : (g < 4) ? g - 2 : g - 4;
    const float* Mbase = (r == 0) ? Mq : (r == 1) ? Mk : Mv;
    for (int i = threadIdx.x; i < 2048; i += blockDim.x) {
        int idx = quarter * 2048 + i;
        int f = idx >> 6, k = idx & 63;
        int head = 2 * p + (f >> 6);
        float v = __ldg(&Mbase[head * 4096 + (f & 63) * 64 + k]);
        __nv_bfloat16 h = __float2bfloat16(v);
        __nv_bfloat16 l = __float2bfloat16(v - __bfloat162float(h));
        int st = g * 8192 + f * 64 + (k >> 4) * 16 + kpos(k & 15);
        g_Wh[st] = h;
        g_Wl[st] = l;
    }
}

// ---- prep X: x1/x2 hi/lo interleaved + scalar pairs ----
__global__ void prep_x(const float* __restrict__ x) {
    const int total = NTOK * 64;
    for (int idx = blockIdx.x * blockDim.x + threadIdx.x; idx < total;
         idx += gridDim.x * blockDim.x) {
        int t = idx >> 6, k = idx & 63;
        int st = t * 64 + (k >> 4) * 16 + kpos(k & 15);
        float v1 = __ldg(&x[t * 130 + k]);
        float v2 = __ldg(&x[t * 130 + 65 + k]);
        __nv_bfloat16 h1 = __float2bfloat16(v1);
        __nv_bfloat16 h2 = __float2bfloat16(v2);
        g_X[0][st] = h1;
        g_X[1][st] = __float2bfloat16(v1 - __bfloat162float(h1));
        g_X[2][st] = h2;
        g_X[3][st] = __float2bfloat16(v2 - __bfloat162float(h2));
        if (k == 0)
            g_S[t] = make_float2(__ldg(&x[t * 130 + 64]), __ldg(&x[t * 130 + 129]));
    }
}

// ---- main: warp = 32 feats x 64 tokens ----
__global__ void __launch_bounds__(256, 2) qkv_mma_kernel(
    const float* __restrict__ Bq, const float* __restrict__ Bk,
    float* __restrict__ out)
{
    const int tid  = threadIdx.x;
    const int wid  = tid >> 5;
    const int lane = tid & 31;
    const int g_   = lane >> 2;          // fragment group (A row / B token / C row)
    const int t4   = lane & 3;           // fragment thread  (k pair / C col)
    const long tok0 = (long)blockIdx.x * 128;

    const int g = blockIdx.y;                       // packed GEMM id
    const int r = (g < 2) ? 0 : (g < 4) ? 1 : 2;    // q / k / v
    const int p = (g < 2) ? g : (g < 4) ? g - 2 : g - 4;
    const int fb = (wid & 3) * 32;       // warp feature base (2x 16-feat tiles)
    const int tc = (wid >> 2) * 64;      // warp token base within CTA

    // A pointers: uint2 index = row*16 + kt*4 + t4  (row stride 64 bf16 = 16 uint2)
    const uint2* Ah = (const uint2*)g_Wh + g * 2048 + (fb + g_) * 16 + t4;
    const uint2* Al = (const uint2*)g_Wl + g * 2048 + (fb + g_) * 16 + t4;
    // B pointers: token row = tok0 + tc + nt*8 + g_
    const __nv_bfloat16* xh = (r == 0) ? g_X[2] : g_X[0];
    const __nv_bfloat16* xl = (r == 0) ? g_X[3] : g_X[1];
    const uint2* Bh = (const uint2*)xh + (tok0 + tc + g_) * 16 + t4;
    const uint2* Bl = (const uint2*)xl + (tok0 + tc + g_) * 16 + t4;

    float c[2][8][4];
    #pragma unroll
    for (int fr = 0; fr < 2; fr++)
        #pragma unroll
        for (int nt = 0; nt < 8; nt++)
            { c[fr][nt][0] = 0.f; c[fr][nt][1] = 0.f;
              c[fr][nt][2] = 0.f; c[fr][nt][3] = 0.f; }

    #pragma unroll
    for (int kt = 0; kt < 4; kt++) {
        // A fragments for both 16-feat row tiles (fr*16 rows = fr*256 uint2)
        uint2 aH0[2], aH1[2], aL0[2], aL1[2];
        #pragma unroll
        for (int fr = 0; fr < 2; fr++) {
            aH0[fr] = __ldg(Ah + fr * 256 + kt * 4);
            aH1[fr] = __ldg(Ah + fr * 256 + 128 + kt * 4);
            aL0[fr] = __ldg(Al + fr * 256 + kt * 4);
            aL1[fr] = __ldg(Al + fr * 256 + 128 + kt * 4);
        }

        #pragma unroll
        for (int nt = 0; nt < 8; nt++) {
            uint2 bH = __ldg(Bh + nt * 128 + kt * 4);   // {b0, b1}
            uint2 bL = __ldg(Bl + nt * 128 + kt * 4);
            #pragma unroll
            for (int fr = 0; fr < 2; fr++) {
                mma_bf16(c[fr][nt], aH0[fr].x, aH1[fr].x, aH0[fr].y, aH1[fr].y, bH.x, bH.y);
                mma_bf16(c[fr][nt], aH0[fr].x, aH1[fr].x, aH0[fr].y, aH1[fr].y, bL.x, bL.y);
                mma_bf16(c[fr][nt], aL0[fr].x, aL1[fr].x, aL0[fr].y, aL1[fr].y, bH.x, bH.y);
            }
        }
    }

    // ---- epilogue: payload stores ----
    float* rbase = out + (long)r * REGION;
    #pragma unroll
    for (int fr = 0; fr < 2; fr++) {
        const int fbase = fb + fr * 16;
        const int head  = 2 * p + (fbase >> 6);
        const int fh    = (fbase & 63) + g_;          // feat-in-head for c0/c1
        float* pbase = rbase + head * 130 + 65;
        #pragma unroll
        for (int nt = 0; nt < 8; nt++) {
            long t0 = tok0 + tc + nt * 8 + 2 * t4;
            float* q0 = pbase + t0 * 1040 + fh;
            q0[0]    = c[fr][nt][0];
            q0[1040] = c[fr][nt][1];
            q0[8]    = c[fr][nt][2];
            q0[1048] = c[fr][nt][3];
        }
    }

    // ---- zeros + scalars: warp wid handles tokens [wid*16, wid*16+16) ----
    {
        const int h0 = 2 * p, h1 = 2 * p + 1, e0 = 4 + 2 * p;
        float tb0 = 0.f, tb1 = 0.f, ebA = 0.f, ebB = 0.f;
        if (r < 2) {
            const float* Bv = r ? Bk : Bq;
            tb0 = __ldg(Bv + h0);        tb1 = __ldg(Bv + h1);
            ebA = __ldg(Bv + 4 + 2 * p); ebB = __ldg(Bv + 5 + 2 * p);
        }
        const float2 z2 = make_float2(0.f, 0.f);
        #pragma unroll 4
        for (int tt = 0; tt < 16; tt++) {
            long tok = tok0 + wid * 16 + tt;
            float* ob = rbase + tok * 1040;
            float2 s = g_S[tok];                     // {s_mid, s_last}

            ((float2*)(ob + h0 * 130))[lane] = z2;   // head h0 slots 0..63
            ((float2*)(ob + h1 * 130))[lane] = z2;   // head h1 slots 0..63

            if (lane == 0) {
                ob[h0 * 130 + 64]  = 0.f;
                ob[h1 * 130 + 64]  = 0.f;
                ob[h0 * 130 + 129] = (r < 2) ? s.y * tb0 : 0.f;
                ob[h1 * 130 + 129] = (r < 2) ? s.y * tb1 : 0.f;
            }

            if (r < 2) {
                // scalar-only heads e0, e0+1: 130 zeros except slot 65
                ((float2*)(ob + e0 * 130))[lane]       = z2;   // 0..63
                ((float2*)(ob + (e0 + 1) * 130))[lane] = z2;
                float sv = (r == 0) ? s.y : s.x;
                float2 vA = (lane == 0) ? make_float2(0.f, sv * ebA) : z2;
                float2 vB = (lane == 0) ? make_float2(0.f, sv * ebB) : z2;
                ((float2*)(ob + e0 * 130 + 64))[lane]       = vA;  // 64..127
                ((float2*)(ob + (e0 + 1) * 130 + 64))[lane] = vB;
                if (lane == 0) {
                    ((float2*)(ob + e0 * 130 + 128))[0]       = z2;  // 128,129
                    ((float2*)(ob + (e0 + 1) * 130 + 128))[0] = z2;
                }
            }
        }
    }
}

extern "C" void kernel_launch(void* const* d_in, const int* in_sizes, int n_in,
                              void* d_out, int out_size) {
    const float* x  = (const float*)d_in[0];
    const float* Mq = (const float*)d_in[1];
    const float* Bq = (const float*)d_in[2];
    const float* Mk = (const float*)d_in[3];
    const float* Bk = (const float*)d_in[4];
    const float* Mv = (const float*)d_in[5];
    float* out = (float*)d_out;

    const int tokens = in_sizes[0] / 130;   // 32768
    prep_w<<<32, 256>>>(Mq, Mk, Mv);
    prep_x<<<256, 256>>>(x);
    dim3 grid(tokens / 128, 8);
    qkv_mma_kernel<<<grid, 256>>>(Bq, Bk, out);
}